// round 13
// baseline (speedup 1.0000x reference)
#include <cuda_runtime.h>
#include <cuda_fp16.h>
#include <cstdint>

#define NMAX 100000
#define EMAX 1600000
#define D    48
#define GMAXG 64
#define HID  128
#define ONUM 12
#define BN_EPS 1e-5f
#define DEGB 1024

// ----------------- static device scratch (no allocs allowed) -----------------
// g_deg / g_hist start zeroed (static init) and are re-zeroed each run.
__device__ int   g_deg[NMAX];
__device__ float g_dinv[NMAX];
__device__ int   g_rowptr[NMAX + 1];
__device__ int   g_rows[EMAX];
__device__ int   g_cols[EMAX];
__device__ int   g_rank[EMAX];
__device__ int2  g_csre[EMAX];       // interleaved (col, w) for gather
__device__ int   g_csr_col[EMAX];    // col-only for maxpool
__device__ int   g_batch[NMAX];
__device__ int   g_hist[DEGB];
__device__ int   g_hoff[DEGB];
__device__ int   g_perm[NMAX];       // nodes sorted by degree
__device__ uint2 g_rowse[NMAX];      // (start,end) per perm slot
__device__ __align__(16) __half g_curh[(size_t)NMAX * D];
__device__ __align__(16) __half g_tx1h[(size_t)NMAX * D];
__device__ __align__(16) __half g_tx2h[(size_t)NMAX * D];
__device__ __align__(16) __half g_th  [(size_t)NMAX * D];
__device__ float g_bnsum[D];
__device__ float g_bnsq[D];
__device__ float g_pool[GMAXG * D];

// ----------------- small helpers -----------------
__device__ __forceinline__ unsigned long long fma2(unsigned long long a,
                                                   unsigned long long b,
                                                   unsigned long long c) {
    unsigned long long d;
    asm("fma.rn.f32x2 %0, %1, %2, %3;" : "=l"(d) : "l"(a), "l"(b), "l"(c));
    return d;
}
__device__ __forceinline__ unsigned long long pack2(float x, float y) {
    unsigned long long d;
    asm("mov.b64 %0, {%1, %2};" : "=l"(d) : "f"(x), "f"(y));
    return d;
}
__device__ __forceinline__ float2 unpack2(unsigned long long v) {
    float2 r;
    asm("mov.b64 {%0, %1}, %2;" : "=f"(r.x), "=f"(r.y) : "l"(v));
    return r;
}
__device__ __forceinline__ uint2 pack_h4(float a, float b, float c, float d) {
    __half2 lo = __floats2half2_rn(a, b);
    __half2 hi = __floats2half2_rn(c, d);
    uint2 o;
    o.x = *(unsigned int*)&lo;
    o.y = *(unsigned int*)&hi;
    return o;
}
__device__ __forceinline__ uint4 pack_h8(const float* a) {
    uint4 o;
    __half2 h0 = __floats2half2_rn(a[0], a[1]);
    __half2 h1 = __floats2half2_rn(a[2], a[3]);
    __half2 h2 = __floats2half2_rn(a[4], a[5]);
    __half2 h3 = __floats2half2_rn(a[6], a[7]);
    o.x = *(unsigned int*)&h0;
    o.y = *(unsigned int*)&h1;
    o.z = *(unsigned int*)&h2;
    o.w = *(unsigned int*)&h3;
    return o;
}

// ----------------- preprocessing (4 launches total) -----------------

__global__ void ingest_kernel(const void* edges, const void* batchp, int E, int N) {
    int mybad = 0;
    if (threadIdx.x < 64) {
        long long v = ((const long long*)edges)[threadIdx.x];
        mybad = (v < 0 || v >= (long long)N) ? 1 : 0;
    }
    int is64 = __syncthreads_or(mybad) ? 0 : 1;

    int i = blockIdx.x * blockDim.x + threadIdx.x;
    if (i < E) {
        int r, c;
        if (is64) {
            r = (int)((const long long*)edges)[i];
            c = (int)((const long long*)edges)[(size_t)E + i];
        } else {
            r = ((const int*)edges)[i];
            c = ((const int*)edges)[E + i];
        }
        g_rows[i] = r;
        g_cols[i] = c;
        g_rank[i] = atomicAdd(&g_deg[r], 1);
    }
    if (i < N) {
        g_batch[i] = is64 ? (int)((const long long*)batchp)[i]
                          : ((const int*)batchp)[i];
    }
}

#define SCAN_CHUNK 2048  // 256 threads * 8

// dinv + rowptr + degree histogram (smem-accumulated, merged to global)
__global__ void rowptr_kernel(int nch, int N) {
    __shared__ int sred[256];
    __shared__ int shist[DEGB];
    int b = blockIdx.x, t = threadIdx.x;
    #pragma unroll
    for (int i = t; i < DEGB; i += 256) shist[i] = 0;

    int pre = b * SCAN_CHUNK;
    int acc = 0;
    for (int i = t; i < pre; i += 256) acc += g_deg[i];
    sred[t] = acc;
    __syncthreads();
    for (int off = 128; off > 0; off >>= 1) {
        if (t < off) sred[t] += sred[t + off];
        __syncthreads();
    }
    __shared__ int sOff;
    if (t == 0) sOff = sred[0];
    __syncthreads();

    __shared__ int sth[256];
    int base = pre + t * 8;
    int vals[8];
    int s = 0;
    #pragma unroll
    for (int i = 0; i < 8; i++) {
        int idx = base + i;
        if (idx < N) {
            int d = g_deg[idx];
            vals[i] = d;
            g_dinv[idx] = (d > 0) ? rsqrtf((float)d) : 0.0f;
            atomicAdd(&shist[min(d, DEGB - 1)], 1);
        } else vals[i] = 0;
        s += vals[i];
    }
    sth[t] = s;
    __syncthreads();
    for (int off = 1; off < 256; off <<= 1) {
        int y = (t >= off) ? sth[t - off] : 0;
        __syncthreads();
        sth[t] += y;
        __syncthreads();
    }
    if (b == nch - 1 && t == 255) g_rowptr[N] = sOff + sth[255];
    int run = sOff + sth[t] - s;
    #pragma unroll
    for (int i = 0; i < 8; i++) {
        int idx = base + i;
        if (idx < N) {
            g_rowptr[idx] = run;
            run += vals[i];
        }
    }
    __syncthreads();
    for (int i = t; i < DEGB; i += 256) {
        int h = shist[i];
        if (h) atomicAdd(&g_hist[i], h);
    }
}

// single block: exclusive scan of degree histogram -> bucket cursors g_hoff;
// re-zero g_hist for replay.
__global__ void histscan_kernel() {
    __shared__ int sh[DEGB];
    int t = threadIdx.x;          // 1024 threads
    int v = g_hist[t];
    g_hist[t] = 0;
    sh[t] = v;
    __syncthreads();
    for (int off = 1; off < DEGB; off <<= 1) {
        int y = (t >= off) ? sh[t - off] : 0;
        __syncthreads();
        sh[t] += y;
        __syncthreads();
    }
    g_hoff[t] = sh[t] - v;        // exclusive prefix
}

// scatter edges to CSR (interleaved + col-only), build degree-sorted perm,
// convert x f32->fp16, reset g_deg.
__global__ void scatconv_kernel(const float* __restrict__ x, int E, int N) {
    int i = blockIdx.x * blockDim.x + threadIdx.x;
    if (i < E) {
        int r = g_rows[i], c = g_cols[i];
        int p = g_rowptr[r] + g_rank[i];
        float w = -g_dinv[r] * g_dinv[c];
        g_csre[p] = make_int2(c, __float_as_int(w));
        g_csr_col[p] = c;
    }
    if (i < N) {
        g_deg[i] = 0;            // replay-safe reset
        int s0 = g_rowptr[i];
        int s1 = g_rowptr[i + 1];
        int d = s1 - s0;
        int pos = atomicAdd(&g_hoff[min(d, DEGB - 1)], 1);
        g_perm[pos] = i;
        g_rowse[pos] = make_uint2((unsigned)s0, (unsigned)s1);
    }
    int ncvt = N * (D / 4);
    if (i < ncvt) {
        float4 v = ((const float4*)x)[i];
        ((uint2*)g_curh)[i] = pack_h4(v.x, v.y, v.z, v.w);
    }
}

// ----------------- main-loop kernels -----------------

// lhat gather (fp16 table, f32x2 accum), group-per-node over degree-sorted perm:
// 6 lanes per node (uint4 = 8 halfs per lane), 5 nodes per warp (lanes 0-29).
__global__ void __launch_bounds__(256) gather_kernel(int sel, int N) {
    const __half* __restrict__ in  = sel ? g_tx1h : g_curh;
    __half*       __restrict__ out = sel ? g_tx2h : g_tx1h;
    if (sel && blockIdx.x == 0 && threadIdx.x < 2 * D) {
        if (threadIdx.x < D) g_bnsum[threadIdx.x] = 0.f;
        else                 g_bnsq[threadIdx.x - D] = 0.f;
    }
    int wid  = blockIdx.x * 8 + (threadIdx.x >> 5);
    int lane = threadIdx.x & 31;
    int gsel = lane / 6;              // 0..4 groups; 5 = idle lanes 30,31
    int fi   = lane - gsel * 6;       // 0..5 (uint4 slot)
    int idx  = wid * 5 + gsel;
    bool nok = (gsel < 5) && (idx < N);
    int node = 0, start = 0, end = 0;
    if (nok) {
        uint2 se = g_rowse[idx];
        start = (int)se.x;
        end   = (int)se.y;
        node  = g_perm[idx];
    }
    int cnt = end - start;
    int warpmax = __reduce_max_sync(0xffffffffu, cnt);
    unsigned long long acc[4] = {0ull, 0ull, 0ull, 0ull};

    int gb6 = gsel * 6;
    for (int b = 0; b < warpmax; b += 6) {
        int p = start + b + fi;
        int cc = 0; float ww = 0.f;
        if (nok && p < end) {
            int2 e = g_csre[p];
            cc = e.x;
            ww = __int_as_float(e.y);
        }
        #pragma unroll
        for (int j = 0; j < 6; j++) {
            int   ci = __shfl_sync(0xffffffffu, cc, (gb6 + j) & 31);
            float wi = __shfl_sync(0xffffffffu, ww, (gb6 + j) & 31);
            if (nok && (b + j < cnt)) {
                const uint4 raw = *reinterpret_cast<const uint4*>(
                    in + (size_t)ci * D + fi * 8);
                float2 f0 = __half22float2(*(__half2*)&raw.x);
                float2 f1 = __half22float2(*(__half2*)&raw.y);
                float2 f2 = __half22float2(*(__half2*)&raw.z);
                float2 f3 = __half22float2(*(__half2*)&raw.w);
                unsigned long long w2 = pack2(wi, wi);
                acc[0] = fma2(pack2(f0.x, f0.y), w2, acc[0]);
                acc[1] = fma2(pack2(f1.x, f1.y), w2, acc[1]);
                acc[2] = fma2(pack2(f2.x, f2.y), w2, acc[2]);
                acc[3] = fma2(pack2(f3.x, f3.y), w2, acc[3]);
            }
        }
    }
    if (nok) {
        float2 a0 = unpack2(acc[0]);
        float2 a1 = unpack2(acc[1]);
        float2 a2 = unpack2(acc[2]);
        float2 a3 = unpack2(acc[3]);
        float a[8] = {a0.x, a0.y, a1.x, a1.y, a2.x, a2.y, a3.x, a3.y};
        *reinterpret_cast<uint4*>(out + (size_t)node * D + fi * 8) = pack_h8(a);
    }
}

// Fused GEMM: t = relu( Tx0*(W0-W2) + Tx1*W1 + Tx2raw*(2W2) + b ), BN stats.
#define SXP 98
__global__ void __launch_bounds__(256) mlp_kernel(const float* __restrict__ W,
                                                  const float* __restrict__ bias,
                                                  int N) {
    __shared__ float sW[3 * 48 * 48];
    __shared__ float sXT[48 * SXP];
    __shared__ float sSum[D], sSq[D];
    int tid = threadIdx.x;
    for (int i = tid; i < 48 * 48; i += 256) {
        float w0 = W[i], w1 = W[2304 + i], w2 = W[4608 + i];
        sW[i]        = w0 - w2;
        sW[2304 + i] = w1;
        sW[4608 + i] = 2.f * w2;
    }
    if (tid < D) { sSum[tid] = 0.f; sSq[tid] = 0.f; }

    int r  = tid >> 4;
    int c  = tid & 15;
    int c3 = c * 3;
    int node_base = blockIdx.x * 96;

    unsigned long long acc[3][3];
    {
        float b0 = bias[c3], b1 = bias[c3 + 1], b2 = bias[c3 + 2];
        #pragma unroll
        for (int pi = 0; pi < 3; pi++) {
            acc[pi][0] = pack2(b0, b0);
            acc[pi][1] = pack2(b1, b1);
            acc[pi][2] = pack2(b2, b2);
        }
    }

    for (int s = 0; s < 3; s++) {
        const __half* src = (s == 0) ? g_curh : (s == 1) ? g_tx1h : g_tx2h;
        __syncthreads();
        for (int i = tid; i < 96 * 12; i += 256) {
            int n = i / 12, q = i % 12;
            int gn = node_base + n;
            uint2 raw = make_uint2(0u, 0u);
            if (gn < N) raw = *(((const uint2*)(src + (size_t)gn * D)) + q);
            float2 lo = __half22float2(*(__half2*)&raw.x);
            float2 hi = __half22float2(*(__half2*)&raw.y);
            int k0 = q * 4;
            sXT[(k0 + 0) * SXP + n] = lo.x;
            sXT[(k0 + 1) * SXP + n] = lo.y;
            sXT[(k0 + 2) * SXP + n] = hi.x;
            sXT[(k0 + 3) * SXP + n] = hi.y;
        }
        __syncthreads();
        const float* wseg = sW + s * 2304;
        #pragma unroll 4
        for (int k = 0; k < 48; k++) {
            float w0 = wseg[k * 48 + c3];
            float w1 = wseg[k * 48 + c3 + 1];
            float w2 = wseg[k * 48 + c3 + 2];
            unsigned long long P0 = pack2(w0, w0);
            unsigned long long P1 = pack2(w1, w1);
            unsigned long long P2 = pack2(w2, w2);
            const float* xrow = &sXT[k * SXP];
            #pragma unroll
            for (int pi = 0; pi < 3; pi++) {
                int p = r + 16 * pi;
                unsigned long long xp =
                    *reinterpret_cast<const unsigned long long*>(xrow + 2 * p);
                acc[pi][0] = fma2(xp, P0, acc[pi][0]);
                acc[pi][1] = fma2(xp, P1, acc[pi][1]);
                acc[pi][2] = fma2(xp, P2, acc[pi][2]);
            }
        }
    }

    float ps[3] = {0, 0, 0}, pq[3] = {0, 0, 0};
    #pragma unroll
    for (int pi = 0; pi < 3; pi++) {
        int p  = r + 16 * pi;
        int n0 = node_base + 2 * p;
        #pragma unroll
        for (int j = 0; j < 3; j++) {
            float2 v = unpack2(acc[pi][j]);
            float v0 = fmaxf(v.x, 0.f);
            float v1 = fmaxf(v.y, 0.f);
            if (n0 < N) {
                g_th[(size_t)n0 * D + c3 + j] = __float2half_rn(v0);
                ps[j] += v0; pq[j] += v0 * v0;
            }
            if (n0 + 1 < N) {
                g_th[(size_t)(n0 + 1) * D + c3 + j] = __float2half_rn(v1);
                ps[j] += v1; pq[j] += v1 * v1;
            }
        }
    }
    __syncthreads();
    #pragma unroll
    for (int j = 0; j < 3; j++) {
        atomicAdd(&sSum[c3 + j], ps[j]);
        atomicAdd(&sSq[c3 + j], pq[j]);
    }
    __syncthreads();
    if (tid < D) {
        atomicAdd(&g_bnsum[tid], sSum[tid]);
        atomicAdd(&g_bnsq[tid],  sSq[tid]);
    }
}

// max-pool over neighbors with BN affine applied, degree-sorted group-per-node.
__global__ void __launch_bounds__(256) maxpool_kernel(const float* __restrict__ gamma,
                                                      const float* __restrict__ beta,
                                                      int N, int G) {
    __shared__ float sScale[D], sShift[D];
    int tid = threadIdx.x;
    int myok = 1;
    if (tid < D) {
        float invn = 1.0f / (float)N;
        float mean = g_bnsum[tid] * invn;
        float var  = g_bnsq[tid] * invn - mean * mean;
        float sc = gamma[tid] * rsqrtf(var + BN_EPS);
        sScale[tid] = sc;
        sShift[tid] = beta[tid] - mean * sc;
        myok = (sc >= 0.f) ? 1 : 0;
    }
    if (blockIdx.x == 0) {
        for (int i = tid; i < G * D; i += 256) g_pool[i] = 0.f;
    }
    int allpos = __syncthreads_and(myok);

    int wid  = blockIdx.x * 8 + (tid >> 5);
    int lane = tid & 31;
    int gsel = lane / 6;
    int fi   = lane - gsel * 6;
    int idx  = wid * 5 + gsel;
    bool nok = (gsel < 5) && (idx < N);
    int node = 0, start = 0, end = 0;
    if (nok) {
        uint2 se = g_rowse[idx];
        start = (int)se.x;
        end   = (int)se.y;
        node  = g_perm[idx];
    }
    int cnt = end - start;
    int warpmax = __reduce_max_sync(0xffffffffu, cnt);
    const float BIG = 3.0e38f;
    float mx[8], mn[8];
    #pragma unroll
    for (int i = 0; i < 8; i++) { mx[i] = -BIG; mn[i] = BIG; }

    int gb6 = gsel * 6;
    if (allpos) {
        for (int b = 0; b < warpmax; b += 6) {
            int p = start + b + fi;
            int cc = 0;
            if (nok && p < end) cc = g_csr_col[p];
            #pragma unroll
            for (int j = 0; j < 6; j++) {
                int ci = __shfl_sync(0xffffffffu, cc, (gb6 + j) & 31);
                if (nok && (b + j < cnt)) {
                    const uint4 raw = *reinterpret_cast<const uint4*>(
                        g_th + (size_t)ci * D + fi * 8);
                    float2 f0 = __half22float2(*(__half2*)&raw.x);
                    float2 f1 = __half22float2(*(__half2*)&raw.y);
                    float2 f2 = __half22float2(*(__half2*)&raw.z);
                    float2 f3 = __half22float2(*(__half2*)&raw.w);
                    mx[0] = fmaxf(mx[0], f0.x);
                    mx[1] = fmaxf(mx[1], f0.y);
                    mx[2] = fmaxf(mx[2], f1.x);
                    mx[3] = fmaxf(mx[3], f1.y);
                    mx[4] = fmaxf(mx[4], f2.x);
                    mx[5] = fmaxf(mx[5], f2.y);
                    mx[6] = fmaxf(mx[6], f3.x);
                    mx[7] = fmaxf(mx[7], f3.y);
                }
            }
        }
    } else {
        for (int b = 0; b < warpmax; b += 6) {
            int p = start + b + fi;
            int cc = 0;
            if (nok && p < end) cc = g_csr_col[p];
            #pragma unroll
            for (int j = 0; j < 6; j++) {
                int ci = __shfl_sync(0xffffffffu, cc, (gb6 + j) & 31);
                if (nok && (b + j < cnt)) {
                    const uint4 raw = *reinterpret_cast<const uint4*>(
                        g_th + (size_t)ci * D + fi * 8);
                    float2 f0 = __half22float2(*(__half2*)&raw.x);
                    float2 f1 = __half22float2(*(__half2*)&raw.y);
                    float2 f2 = __half22float2(*(__half2*)&raw.z);
                    float2 f3 = __half22float2(*(__half2*)&raw.w);
                    float v[8] = {f0.x, f0.y, f1.x, f1.y, f2.x, f2.y, f3.x, f3.y};
                    #pragma unroll
                    for (int q = 0; q < 8; q++) {
                        mx[q] = fmaxf(mx[q], v[q]);
                        mn[q] = fminf(mn[q], v[q]);
                    }
                }
            }
        }
    }
    if (nok) {
        float o[8];
        if (cnt == 0) {
            #pragma unroll
            for (int q = 0; q < 8; q++) o[q] = 0.f;
        } else {
            #pragma unroll
            for (int q = 0; q < 8; q++) {
                float sc = sScale[fi * 8 + q];
                float sh = sShift[fi * 8 + q];
                float v = (allpos || sc >= 0.f) ? mx[q] : mn[q];
                o[q] = fmaf(v, sc, sh);
            }
        }
        *reinterpret_cast<uint4*>(g_curh + (size_t)node * D + fi * 8) = pack_h8(o);
    }
}

// ----------------- readout -----------------

__global__ void sumpool_kernel(int N) {
    int d = threadIdx.x;                 // 0..47
    int chunk = blockIdx.x * blockDim.y + threadIdx.y;
    int n0 = chunk * 64;
    if (n0 >= N) return;
    int n1 = min(n0 + 64, N);
    float acc = 0.f;
    int curb = g_batch[n0];
    for (int n = n0; n < n1; n++) {
        int bb = g_batch[n];
        if (bb != curb) {
            atomicAdd(&g_pool[curb * D + d], acc);
            acc = 0.f;
            curb = bb;
        }
        acc += __half2float(g_curh[(size_t)n * D + d]);
    }
    atomicAdd(&g_pool[curb * D + d], acc);
}

__global__ void head_kernel(const float* __restrict__ W1, const float* __restrict__ b1,
                            const float* __restrict__ W2, const float* __restrict__ b2,
                            float* __restrict__ out) {
    __shared__ float sg[D];
    __shared__ float sh[HID];
    int gidx = blockIdx.x;
    int t = threadIdx.x;
    if (t < D) sg[t] = g_pool[gidx * D + t];
    __syncthreads();
    float acc = b1[t];
    #pragma unroll 4
    for (int k = 0; k < D; k++) acc = fmaf(sg[k], W1[k * HID + t], acc);
    sh[t] = fmaxf(acc, 0.f);
    __syncthreads();
    if (t < ONUM) {
        float o = b2[t];
        #pragma unroll 4
        for (int j = 0; j < HID; j++) o = fmaf(sh[j], W2[j * ONUM + t], o);
        out[gidx * ONUM + t] = o;
    }
}

// ----------------- launch -----------------

extern "C" void kernel_launch(void* const* d_in, const int* in_sizes, int n_in,
                              void* d_out, int out_size) {
    const float* x      = (const float*)d_in[0];
    const void*  edges  = d_in[1];
    const void*  batchp = d_in[2];
    int N = in_sizes[0] / D;
    int E = in_sizes[1] / 2;

    int wi = 3;
    while (wi < n_in && in_sizes[wi] != 3 * D * D) wi++;
    const float* W     = (const float*)d_in[wi];
    const float* b     = (const float*)d_in[wi + 1];
    const float* gamma = (const float*)d_in[wi + 2];
    const float* beta  = (const float*)d_in[wi + 3];
    const float* W1    = (const float*)d_in[wi + 4];
    const float* b1    = (const float*)d_in[wi + 5];
    const float* W2    = (const float*)d_in[wi + 6];
    const float* b2    = (const float*)d_in[wi + 7];
    float* out = (float*)d_out;
    int G = out_size / ONUM;

    int nch = (N + SCAN_CHUNK - 1) / SCAN_CHUNK;

    {
        int m = (E > N ? E : N);
        ingest_kernel<<<(m + 255) / 256, 256>>>(edges, batchp, E, N);
    }
    rowptr_kernel<<<nch, 256>>>(nch, N);
    histscan_kernel<<<1, DEGB>>>();
    {
        int ncvt = N * (D / 4);
        int m = (E > ncvt ? E : ncvt);
        if (N > m) m = N;
        scatconv_kernel<<<(m + 255) / 256, 256>>>(x, E, N);
    }

    int gb = (N + 39) / 40;   // 8 warps/block, 5 nodes/warp
    for (int it = 0; it < 5; it++) {
        gather_kernel<<<gb, 256>>>(0, N);
        gather_kernel<<<gb, 256>>>(1, N);
        mlp_kernel<<<(N + 95) / 96, 256>>>(W, b, N);
        maxpool_kernel<<<gb, 256>>>(gamma, beta, N, G);
    }

    {
        int chunks = (N + 63) / 64;
        dim3 bdim(D, 4);
        sumpool_kernel<<<(chunks + 3) / 4, bdim>>>(N);
    }
    head_kernel<<<G, HID>>>(W1, b1, W2, b2, out);
}

// round 14
// speedup vs baseline: 1.0210x; 1.0210x over previous
#include <cuda_runtime.h>
#include <cuda_fp16.h>
#include <cstdint>

#define NMAX 100000
#define EMAX 1600000
#define D    48
#define GMAXG 64
#define HID  128
#define ONUM 12
#define BN_EPS 1e-5f

// ----------------- static device scratch (no allocs allowed) -----------------
// g_deg starts zeroed (static init) and is re-zeroed by scatconv each run.
__device__ int   g_deg[NMAX];
__device__ float g_dinv[NMAX];
__device__ int   g_rowptr[NMAX + 1];
__device__ int   g_rows[EMAX];
__device__ int   g_cols[EMAX];
__device__ int   g_rank[EMAX];
__device__ int2  g_csre[EMAX];       // interleaved (col, w as replicated half2)
__device__ int   g_batch[NMAX];
__device__ __align__(16) __half g_curh[(size_t)NMAX * D];
__device__ __align__(16) __half g_tx1h[(size_t)NMAX * D];
__device__ __align__(16) __half g_tx2h[(size_t)NMAX * D];
__device__ __align__(16) __half g_th  [(size_t)NMAX * D];
__device__ float g_bnsum[D];
__device__ float g_bnsq[D];
__device__ float g_pool[GMAXG * D];

// ----------------- small helpers -----------------
__device__ __forceinline__ unsigned long long fma2(unsigned long long a,
                                                   unsigned long long b,
                                                   unsigned long long c) {
    unsigned long long d;
    asm("fma.rn.f32x2 %0, %1, %2, %3;" : "=l"(d) : "l"(a), "l"(b), "l"(c));
    return d;
}
__device__ __forceinline__ unsigned long long pack2(float x, float y) {
    unsigned long long d;
    asm("mov.b64 %0, {%1, %2};" : "=l"(d) : "f"(x), "f"(y));
    return d;
}
__device__ __forceinline__ float2 unpack2(unsigned long long v) {
    float2 r;
    asm("mov.b64 {%0, %1}, %2;" : "=f"(r.x), "=f"(r.y) : "l"(v));
    return r;
}
__device__ __forceinline__ uint2 pack_h4(float a, float b, float c, float d) {
    __half2 lo = __floats2half2_rn(a, b);
    __half2 hi = __floats2half2_rn(c, d);
    uint2 o;
    o.x = *(unsigned int*)&lo;
    o.y = *(unsigned int*)&hi;
    return o;
}
__device__ __forceinline__ uint4 pack_h8(const float* a) {
    uint4 o;
    __half2 h0 = __floats2half2_rn(a[0], a[1]);
    __half2 h1 = __floats2half2_rn(a[2], a[3]);
    __half2 h2 = __floats2half2_rn(a[4], a[5]);
    __half2 h3 = __floats2half2_rn(a[6], a[7]);
    o.x = *(unsigned int*)&h0;
    o.y = *(unsigned int*)&h1;
    o.z = *(unsigned int*)&h2;
    o.w = *(unsigned int*)&h3;
    return o;
}

// ----------------- preprocessing (3 launches total) -----------------

__global__ void ingest_kernel(const void* edges, const void* batchp, int E, int N) {
    int mybad = 0;
    if (threadIdx.x < 64) {
        long long v = ((const long long*)edges)[threadIdx.x];
        mybad = (v < 0 || v >= (long long)N) ? 1 : 0;
    }
    int is64 = __syncthreads_or(mybad) ? 0 : 1;

    int i = blockIdx.x * blockDim.x + threadIdx.x;
    if (i < E) {
        int r, c;
        if (is64) {
            r = (int)((const long long*)edges)[i];
            c = (int)((const long long*)edges)[(size_t)E + i];
        } else {
            r = ((const int*)edges)[i];
            c = ((const int*)edges)[E + i];
        }
        g_rows[i] = r;
        g_cols[i] = c;
        g_rank[i] = atomicAdd(&g_deg[r], 1);
    }
    if (i < N) {
        g_batch[i] = is64 ? (int)((const long long*)batchp)[i]
                          : ((const int*)batchp)[i];
    }
}

#define SCAN_CHUNK 2048  // 256 threads * 8

__global__ void rowptr_kernel(int nch, int N) {
    __shared__ int sred[256];
    int b = blockIdx.x, t = threadIdx.x;

    int pre = b * SCAN_CHUNK;
    int acc = 0;
    for (int i = t; i < pre; i += 256) acc += g_deg[i];
    sred[t] = acc;
    __syncthreads();
    for (int off = 128; off > 0; off >>= 1) {
        if (t < off) sred[t] += sred[t + off];
        __syncthreads();
    }
    __shared__ int sOff;
    if (t == 0) sOff = sred[0];
    __syncthreads();

    __shared__ int sth[256];
    int base = pre + t * 8;
    int vals[8];
    int s = 0;
    #pragma unroll
    for (int i = 0; i < 8; i++) {
        int idx = base + i;
        if (idx < N) {
            int d = g_deg[idx];
            vals[i] = d;
            g_dinv[idx] = (d > 0) ? rsqrtf((float)d) : 0.0f;
        } else vals[i] = 0;
        s += vals[i];
    }
    sth[t] = s;
    __syncthreads();
    for (int off = 1; off < 256; off <<= 1) {
        int y = (t >= off) ? sth[t - off] : 0;
        __syncthreads();
        sth[t] += y;
        __syncthreads();
    }
    if (b == nch - 1 && t == 255) g_rowptr[N] = sOff + sth[255];
    int run = sOff + sth[t] - s;
    #pragma unroll
    for (int i = 0; i < 8; i++) {
        int idx = base + i;
        if (idx < N) {
            g_rowptr[idx] = run;
            run += vals[i];
        }
    }
}

// scatter edges to CSR (col, fp16-replicated weight) + x f32->fp16 + deg reset
__global__ void scatconv_kernel(const float* __restrict__ x, int E, int N) {
    int i = blockIdx.x * blockDim.x + threadIdx.x;
    if (i < E) {
        int r = g_rows[i], c = g_cols[i];
        int p = g_rowptr[r] + g_rank[i];
        float w = -g_dinv[r] * g_dinv[c];
        __half2 w2 = __floats2half2_rn(w, w);
        g_csre[p] = make_int2(c, *(int*)&w2);
    }
    if (i < N) g_deg[i] = 0;     // replay-safe reset
    int ncvt = N * (D / 4);
    if (i < ncvt) {
        float4 v = ((const float4*)x)[i];
        ((uint2*)g_curh)[i] = pack_h4(v.x, v.y, v.z, v.w);
    }
}

// ----------------- main-loop kernels -----------------

// lhat gather: fp16 table, HFMA2 accumulation within each 6-edge chunk,
// fp32 group merge. 6 lanes per node (uint4 = 8 halfs/lane), 5 nodes/warp.
// Invalid edge slots carry w=0 -> branchless inner loop.
__global__ void __launch_bounds__(256) gather_kernel(int sel, int N) {
    const __half* __restrict__ in  = sel ? g_tx1h : g_curh;
    __half*       __restrict__ out = sel ? g_tx2h : g_tx1h;
    if (sel && blockIdx.x == 0 && threadIdx.x < 2 * D) {
        if (threadIdx.x < D) g_bnsum[threadIdx.x] = 0.f;
        else                 g_bnsq[threadIdx.x - D] = 0.f;
    }
    int wid  = blockIdx.x * 8 + (threadIdx.x >> 5);
    int lane = threadIdx.x & 31;
    int gsel = lane / 6;              // 0..4 groups; 5 = idle lanes 30,31
    int fi   = lane - gsel * 6;       // 0..5 (uint4 slot)
    int node = wid * 5 + gsel;
    bool nok = (gsel < 5) && (node < N);
    int start = 0, end = 0;
    if (nok) {
        start = g_rowptr[node];
        end   = g_rowptr[node + 1];
    }
    int cnt = end - start;
    int warpmax = __reduce_max_sync(0xffffffffu, cnt);
    float a[8];
    #pragma unroll
    for (int i = 0; i < 8; i++) a[i] = 0.f;

    int gb6 = gsel * 6;
    const __half2 hz = __float2half2_rn(0.f);
    for (int b = 0; b < warpmax; b += 6) {
        int p = start + b + fi;
        int cc = 0; unsigned wu = 0;      // w=0 for invalid slots
        if (nok && p < end) {
            int2 e = g_csre[p];
            cc = e.x;
            wu = (unsigned)e.y;
        }
        __half2 h0 = hz, h1 = hz, h2 = hz, h3 = hz;
        #pragma unroll
        for (int j = 0; j < 6; j++) {
            int      ci = __shfl_sync(0xffffffffu, cc, (gb6 + j) & 31);
            unsigned wb = __shfl_sync(0xffffffffu, wu, (gb6 + j) & 31);
            __half2 w2 = *(__half2*)&wb;
            const uint4 raw = *reinterpret_cast<const uint4*>(
                in + (size_t)ci * D + fi * 8);
            h0 = __hfma2(*(__half2*)&raw.x, w2, h0);
            h1 = __hfma2(*(__half2*)&raw.y, w2, h1);
            h2 = __hfma2(*(__half2*)&raw.z, w2, h2);
            h3 = __hfma2(*(__half2*)&raw.w, w2, h3);
        }
        float2 f0 = __half22float2(h0);
        float2 f1 = __half22float2(h1);
        float2 f2 = __half22float2(h2);
        float2 f3 = __half22float2(h3);
        a[0] += f0.x; a[1] += f0.y;
        a[2] += f1.x; a[3] += f1.y;
        a[4] += f2.x; a[5] += f2.y;
        a[6] += f3.x; a[7] += f3.y;
    }
    if (nok) {
        *reinterpret_cast<uint4*>(out + (size_t)node * D + fi * 8) = pack_h8(a);
    }
}

// Fused GEMM: t = relu( Tx0*(W0-W2) + Tx1*W1 + Tx2raw*(2W2) + b ), BN stats.
#define SXP 98
__global__ void __launch_bounds__(256) mlp_kernel(const float* __restrict__ W,
                                                  const float* __restrict__ bias,
                                                  int N) {
    __shared__ float sW[3 * 48 * 48];
    __shared__ float sXT[48 * SXP];
    __shared__ float sSum[D], sSq[D];
    int tid = threadIdx.x;
    for (int i = tid; i < 48 * 48; i += 256) {
        float w0 = W[i], w1 = W[2304 + i], w2 = W[4608 + i];
        sW[i]        = w0 - w2;
        sW[2304 + i] = w1;
        sW[4608 + i] = 2.f * w2;
    }
    if (tid < D) { sSum[tid] = 0.f; sSq[tid] = 0.f; }

    int r  = tid >> 4;
    int c  = tid & 15;
    int c3 = c * 3;
    int node_base = blockIdx.x * 96;

    unsigned long long acc[3][3];
    {
        float b0 = bias[c3], b1 = bias[c3 + 1], b2 = bias[c3 + 2];
        #pragma unroll
        for (int pi = 0; pi < 3; pi++) {
            acc[pi][0] = pack2(b0, b0);
            acc[pi][1] = pack2(b1, b1);
            acc[pi][2] = pack2(b2, b2);
        }
    }

    for (int s = 0; s < 3; s++) {
        const __half* src = (s == 0) ? g_curh : (s == 1) ? g_tx1h : g_tx2h;
        __syncthreads();
        for (int i = tid; i < 96 * 12; i += 256) {
            int n = i / 12, q = i % 12;
            int gn = node_base + n;
            uint2 raw = make_uint2(0u, 0u);
            if (gn < N) raw = *(((const uint2*)(src + (size_t)gn * D)) + q);
            float2 lo = __half22float2(*(__half2*)&raw.x);
            float2 hi = __half22float2(*(__half2*)&raw.y);
            int k0 = q * 4;
            sXT[(k0 + 0) * SXP + n] = lo.x;
            sXT[(k0 + 1) * SXP + n] = lo.y;
            sXT[(k0 + 2) * SXP + n] = hi.x;
            sXT[(k0 + 3) * SXP + n] = hi.y;
        }
        __syncthreads();
        const float* wseg = sW + s * 2304;
        #pragma unroll 4
        for (int k = 0; k < 48; k++) {
            float w0 = wseg[k * 48 + c3];
            float w1 = wseg[k * 48 + c3 + 1];
            float w2 = wseg[k * 48 + c3 + 2];
            unsigned long long P0 = pack2(w0, w0);
            unsigned long long P1 = pack2(w1, w1);
            unsigned long long P2 = pack2(w2, w2);
            const float* xrow = &sXT[k * SXP];
            #pragma unroll
            for (int pi = 0; pi < 3; pi++) {
                int p = r + 16 * pi;
                unsigned long long xp =
                    *reinterpret_cast<const unsigned long long*>(xrow + 2 * p);
                acc[pi][0] = fma2(xp, P0, acc[pi][0]);
                acc[pi][1] = fma2(xp, P1, acc[pi][1]);
                acc[pi][2] = fma2(xp, P2, acc[pi][2]);
            }
        }
    }

    float ps[3] = {0, 0, 0}, pq[3] = {0, 0, 0};
    #pragma unroll
    for (int pi = 0; pi < 3; pi++) {
        int p  = r + 16 * pi;
        int n0 = node_base + 2 * p;
        #pragma unroll
        for (int j = 0; j < 3; j++) {
            float2 v = unpack2(acc[pi][j]);
            float v0 = fmaxf(v.x, 0.f);
            float v1 = fmaxf(v.y, 0.f);
            if (n0 < N) {
                g_th[(size_t)n0 * D + c3 + j] = __float2half_rn(v0);
                ps[j] += v0; pq[j] += v0 * v0;
            }
            if (n0 + 1 < N) {
                g_th[(size_t)(n0 + 1) * D + c3 + j] = __float2half_rn(v1);
                ps[j] += v1; pq[j] += v1 * v1;
            }
        }
    }
    __syncthreads();
    #pragma unroll
    for (int j = 0; j < 3; j++) {
        atomicAdd(&sSum[c3 + j], ps[j]);
        atomicAdd(&sSq[c3 + j], pq[j]);
    }
    __syncthreads();
    if (tid < D) {
        atomicAdd(&g_bnsum[tid], sSum[tid]);
        atomicAdd(&g_bnsq[tid],  sSq[tid]);
    }
}

// max-pool over neighbors with BN affine applied. Fast path uses exact fp16
// HMAX2 tracking (comparison only, no rounding); affine applied in fp32.
__global__ void __launch_bounds__(256) maxpool_kernel(const float* __restrict__ gamma,
                                                      const float* __restrict__ beta,
                                                      int N, int G) {
    __shared__ float sScale[D], sShift[D];
    int tid = threadIdx.x;
    int myok = 1;
    if (tid < D) {
        float invn = 1.0f / (float)N;
        float mean = g_bnsum[tid] * invn;
        float var  = g_bnsq[tid] * invn - mean * mean;
        float sc = gamma[tid] * rsqrtf(var + BN_EPS);
        sScale[tid] = sc;
        sShift[tid] = beta[tid] - mean * sc;
        myok = (sc >= 0.f) ? 1 : 0;
    }
    if (blockIdx.x == 0) {
        for (int i = tid; i < G * D; i += 256) g_pool[i] = 0.f;
    }
    int allpos = __syncthreads_and(myok);

    int wid  = blockIdx.x * 8 + (tid >> 5);
    int lane = tid & 31;
    int gsel = lane / 6;
    int fi   = lane - gsel * 6;
    int node = wid * 5 + gsel;
    bool nok = (gsel < 5) && (node < N);
    int start = 0, end = 0;
    if (nok) {
        start = g_rowptr[node];
        end   = g_rowptr[node + 1];
    }
    int cnt = end - start;
    int warpmax = __reduce_max_sync(0xffffffffu, cnt);
    int gb6 = gsel * 6;

    if (allpos) {
        // fp16 max tracking (exact)
        unsigned ninf = 0xFC00FC00u;    // (-inf, -inf) half2
        __half2 m0 = *(__half2*)&ninf, m1 = m0, m2 = m0, m3 = m0;
        for (int b = 0; b < warpmax; b += 6) {
            int p = start + b + fi;
            int cc = 0;
            if (nok && p < end) cc = g_csre[p].x;
            #pragma unroll
            for (int j = 0; j < 6; j++) {
                int ci = __shfl_sync(0xffffffffu, cc, (gb6 + j) & 31);
                if (nok && (b + j < cnt)) {
                    const uint4 raw = *reinterpret_cast<const uint4*>(
                        g_th + (size_t)ci * D + fi * 8);
                    m0 = __hmax2(m0, *(__half2*)&raw.x);
                    m1 = __hmax2(m1, *(__half2*)&raw.y);
                    m2 = __hmax2(m2, *(__half2*)&raw.z);
                    m3 = __hmax2(m3, *(__half2*)&raw.w);
                }
            }
        }
        if (nok) {
            float o[8];
            if (cnt == 0) {
                #pragma unroll
                for (int q = 0; q < 8; q++) o[q] = 0.f;
            } else {
                float2 f0 = __half22float2(m0);
                float2 f1 = __half22float2(m1);
                float2 f2 = __half22float2(m2);
                float2 f3 = __half22float2(m3);
                float v[8] = {f0.x, f0.y, f1.x, f1.y, f2.x, f2.y, f3.x, f3.y};
                #pragma unroll
                for (int q = 0; q < 8; q++)
                    o[q] = fmaf(v[q], sScale[fi * 8 + q], sShift[fi * 8 + q]);
            }
            *reinterpret_cast<uint4*>(g_curh + (size_t)node * D + fi * 8) = pack_h8(o);
        }
    } else {
        // rare path: fp32 min+max tracking
        const float BIG = 3.0e38f;
        float mx[8], mn[8];
        #pragma unroll
        for (int i = 0; i < 8; i++) { mx[i] = -BIG; mn[i] = BIG; }
        for (int b = 0; b < warpmax; b += 6) {
            int p = start + b + fi;
            int cc = 0;
            if (nok && p < end) cc = g_csre[p].x;
            #pragma unroll
            for (int j = 0; j < 6; j++) {
                int ci = __shfl_sync(0xffffffffu, cc, (gb6 + j) & 31);
                if (nok && (b + j < cnt)) {
                    const uint4 raw = *reinterpret_cast<const uint4*>(
                        g_th + (size_t)ci * D + fi * 8);
                    float2 f0 = __half22float2(*(__half2*)&raw.x);
                    float2 f1 = __half22float2(*(__half2*)&raw.y);
                    float2 f2 = __half22float2(*(__half2*)&raw.z);
                    float2 f3 = __half22float2(*(__half2*)&raw.w);
                    float v[8] = {f0.x, f0.y, f1.x, f1.y, f2.x, f2.y, f3.x, f3.y};
                    #pragma unroll
                    for (int q = 0; q < 8; q++) {
                        mx[q] = fmaxf(mx[q], v[q]);
                        mn[q] = fminf(mn[q], v[q]);
                    }
                }
            }
        }
        if (nok) {
            float o[8];
            if (cnt == 0) {
                #pragma unroll
                for (int q = 0; q < 8; q++) o[q] = 0.f;
            } else {
                #pragma unroll
                for (int q = 0; q < 8; q++) {
                    float sc = sScale[fi * 8 + q];
                    float sh = sShift[fi * 8 + q];
                    float v = (sc >= 0.f) ? mx[q] : mn[q];
                    o[q] = fmaf(v, sc, sh);
                }
            }
            *reinterpret_cast<uint4*>(g_curh + (size_t)node * D + fi * 8) = pack_h8(o);
        }
    }
}

// ----------------- readout -----------------

__global__ void sumpool_kernel(int N) {
    int d = threadIdx.x;                 // 0..47
    int chunk = blockIdx.x * blockDim.y + threadIdx.y;
    int n0 = chunk * 64;
    if (n0 >= N) return;
    int n1 = min(n0 + 64, N);
    float acc = 0.f;
    int curb = g_batch[n0];
    for (int n = n0; n < n1; n++) {
        int bb = g_batch[n];
        if (bb != curb) {
            atomicAdd(&g_pool[curb * D + d], acc);
            acc = 0.f;
            curb = bb;
        }
        acc += __half2float(g_curh[(size_t)n * D + d]);
    }
    atomicAdd(&g_pool[curb * D + d], acc);
}

__global__ void head_kernel(const float* __restrict__ W1, const float* __restrict__ b1,
                            const float* __restrict__ W2, const float* __restrict__ b2,
                            float* __restrict__ out) {
    __shared__ float sg[D];
    __shared__ float sh[HID];
    int gidx = blockIdx.x;
    int t = threadIdx.x;
    if (t < D) sg[t] = g_pool[gidx * D + t];
    __syncthreads();
    float acc = b1[t];
    #pragma unroll 4
    for (int k = 0; k < D; k++) acc = fmaf(sg[k], W1[k * HID + t], acc);
    sh[t] = fmaxf(acc, 0.f);
    __syncthreads();
    if (t < ONUM) {
        float o = b2[t];
        #pragma unroll 4
        for (int j = 0; j < HID; j++) o = fmaf(sh[j], W2[j * ONUM + t], o);
        out[gidx * ONUM + t] = o;
    }
}

// ----------------- launch -----------------

extern "C" void kernel_launch(void* const* d_in, const int* in_sizes, int n_in,
                              void* d_out, int out_size) {
    const float* x      = (const float*)d_in[0];
    const void*  edges  = d_in[1];
    const void*  batchp = d_in[2];
    int N = in_sizes[0] / D;
    int E = in_sizes[1] / 2;

    int wi = 3;
    while (wi < n_in && in_sizes[wi] != 3 * D * D) wi++;
    const float* W     = (const float*)d_in[wi];
    const float* b     = (const float*)d_in[wi + 1];
    const float* gamma = (const float*)d_in[wi + 2];
    const float* beta  = (const float*)d_in[wi + 3];
    const float* W1    = (const float*)d_in[wi + 4];
    const float* b1    = (const float*)d_in[wi + 5];
    const float* W2    = (const float*)d_in[wi + 6];
    const float* b2    = (const float*)d_in[wi + 7];
    float* out = (float*)d_out;
    int G = out_size / ONUM;

    int nch = (N + SCAN_CHUNK - 1) / SCAN_CHUNK;

    {
        int m = (E > N ? E : N);
        ingest_kernel<<<(m + 255) / 256, 256>>>(edges, batchp, E, N);   // slot 0
    }
    rowptr_kernel<<<nch, 256>>>(nch, N);                                // slot 1
    {
        int ncvt = N * (D / 4);
        int m = (E > ncvt ? E : ncvt);
        if (N > m) m = N;
        scatconv_kernel<<<(m + 255) / 256, 256>>>(x, E, N);             // slot 2
    }

    int gb = (N + 39) / 40;   // 8 warps/block, 5 nodes/warp
    for (int it = 0; it < 5; it++) {
        gather_kernel<<<gb, 256>>>(0, N);            // slot 3 on it=0: PROFILED
        gather_kernel<<<gb, 256>>>(1, N);
        mlp_kernel<<<(N + 95) / 96, 256>>>(W, b, N);
        maxpool_kernel<<<gb, 256>>>(gamma, beta, N, G);
    }

    {
        int chunks = (N + 63) / 64;
        dim3 bdim(D, 4);
        sumpool_kernel<<<(chunks + 3) / 4, bdim>>>(N);
    }
    head_kernel<<<G, HID>>>(W1, b1, W2, b2, out);
}